// round 4
// baseline (speedup 1.0000x reference)
#include <cuda_runtime.h>

// Scratch: flat argmax indices per (b*c, p). 128 * 256 ints. No device allocation.
__device__ int g_idx[128 * 256];

// Kernel 1: 2x2/stride-2 maxpool with flat argmax over H*W=1024.
// Grid: 128 blocks (one per (b,c)), 256 threads (one per output pixel).
__global__ void pool_argmax_kernel(const float* __restrict__ mu,
                                   float* __restrict__ out_mu) {
    const int bc = blockIdx.x;            // 0..127
    const int p  = threadIdx.x;           // 0..255, p = ho*16 + wo
    const int ho = p >> 4;
    const int wo = p & 15;

    const float* base = mu + (size_t)bc * 1024;   // 32x32 image
    const int r0 = 2 * ho;
    const int c0 = 2 * wo;

    // Window order matches reference: [dy,dx] flattened -> k = dy*2 + dx.
    const float v0 = base[r0 * 32 + c0];
    const float v1 = base[r0 * 32 + c0 + 1];
    const float v2 = base[(r0 + 1) * 32 + c0];
    const float v3 = base[(r0 + 1) * 32 + c0 + 1];

    float m = v0; int k = 0;
    if (v1 > m) { m = v1; k = 1; }        // strict > keeps FIRST max (jnp.argmax)
    if (v2 > m) { m = v2; k = 2; }
    if (v3 > m) { m = v3; k = 3; }

    const int row = r0 + (k >> 1);
    const int col = c0 + (k & 1);

    g_idx[bc * 256 + p]  = row * 32 + col;
    out_mu[bc * 256 + p] = m;
}

// Kernel 2: sigma_p[bc, i, j] = sigma[bc, idx[i], idx[j]].
// Grid: 128 bc * 8 row-chunks = 1024 blocks, 256 threads (one per output column j).
// Output writes are fully coalesced; gather reads touch every 32B sector of the
// 256 selected rows exactly once (DRAM-bound floor for this pattern).
__global__ void sigma_gather_kernel(const float* __restrict__ sigma,
                                    float* __restrict__ out_sig) {
    __shared__ int scol[256];

    const int bc    = blockIdx.x >> 3;    // 0..127
    const int chunk = blockIdx.x & 7;     // 0..7  (32 output rows each)
    const int j     = threadIdx.x;        // 0..255

    scol[j] = g_idx[bc * 256 + j];
    __syncthreads();

    const int cj = scol[j];                                // this thread's column
    const float* sbase = sigma   + (size_t)bc * 1024 * 1024;
    float*       obase = out_sig + (size_t)bc * 65536;

    const int i0 = chunk * 32;
    #pragma unroll 4
    for (int i = i0; i < i0 + 32; ++i) {
        const int ri = scol[i];                            // broadcast LDS
        obase[(size_t)i * 256 + j] = __ldg(sbase + (size_t)ri * 1024 + cj);
    }
}

extern "C" void kernel_launch(void* const* d_in, const int* in_sizes, int n_in,
                              void* d_out, int out_size) {
    // Inputs per metadata order: mu [8,16,32,32] f32, sigma [8,16,1024,1024] f32.
    // Identify by size to be robust to ordering.
    const float* mu    = (const float*)d_in[0];
    const float* sigma = (const float*)d_in[1];
    if (n_in >= 2 && in_sizes[0] > in_sizes[1]) {
        sigma = (const float*)d_in[0];
        mu    = (const float*)d_in[1];
    }

    float* out_mu  = (float*)d_out;            // 8*16*16*16 = 32768 elements
    float* out_sig = out_mu + 32768;           // 8*16*256*256 = 8388608 elements

    pool_argmax_kernel<<<128, 256>>>(mu, out_mu);
    sigma_gather_kernel<<<1024, 256>>>(sigma, out_sig);
}

// round 5
// speedup vs baseline: 1.0077x; 1.0077x over previous
#include <cuda_runtime.h>

// Scratch: flat argmax indices per (b*c, p). 128 * 256 ints. No device allocation.
__device__ int g_idx[128 * 256];

// Kernel 1: 2x2/stride-2 maxpool with flat argmax over H*W=1024.
// Grid: 128 blocks (one per (b,c)), 256 threads (one per output pixel).
__global__ void pool_argmax_kernel(const float* __restrict__ mu,
                                   float* __restrict__ out_mu) {
    const int bc = blockIdx.x;            // 0..127
    const int p  = threadIdx.x;           // 0..255, p = ho*16 + wo
    const int ho = p >> 4;
    const int wo = p & 15;

    const float* base = mu + (size_t)bc * 1024;   // 32x32 image
    const int r0 = 2 * ho;
    const int c0 = 2 * wo;

    // Window order matches reference: [dy,dx] flattened -> k = dy*2 + dx.
    const float v0 = base[r0 * 32 + c0];
    const float v1 = base[r0 * 32 + c0 + 1];
    const float v2 = base[(r0 + 1) * 32 + c0];
    const float v3 = base[(r0 + 1) * 32 + c0 + 1];

    float m = v0; int k = 0;
    if (v1 > m) { m = v1; k = 1; }        // strict > keeps FIRST max (jnp.argmax)
    if (v2 > m) { m = v2; k = 2; }
    if (v3 > m) { m = v3; k = 3; }

    const int row = r0 + (k >> 1);
    const int col = c0 + (k & 1);

    g_idx[bc * 256 + p]  = row * 32 + col;
    out_mu[bc * 256 + p] = m;
}

// Kernel 2: sigma_p[bc, i, j] = sigma[bc, idx[i], idx[j]].
// Grid: 128 bc * 8 row-chunks = 1024 blocks, 256 threads (one per output column j).
// Output writes are fully coalesced; gather reads touch every 32B sector of the
// 256 selected rows exactly once (DRAM-bound floor for this pattern).
__global__ void sigma_gather_kernel(const float* __restrict__ sigma,
                                    float* __restrict__ out_sig) {
    __shared__ int scol[256];

    const int bc    = blockIdx.x >> 3;    // 0..127
    const int chunk = blockIdx.x & 7;     // 0..7  (32 output rows each)
    const int j     = threadIdx.x;        // 0..255

    scol[j] = g_idx[bc * 256 + j];
    __syncthreads();

    const int cj = scol[j];                                // this thread's column
    const float* sbase = sigma   + (size_t)bc * 1024 * 1024;
    float*       obase = out_sig + (size_t)bc * 65536;

    const int i0 = chunk * 32;
    #pragma unroll 4
    for (int i = i0; i < i0 + 32; ++i) {
        const int ri = scol[i];                            // broadcast LDS
        obase[(size_t)i * 256 + j] = __ldg(sbase + (size_t)ri * 1024 + cj);
    }
}

extern "C" void kernel_launch(void* const* d_in, const int* in_sizes, int n_in,
                              void* d_out, int out_size) {
    // Inputs per metadata order: mu [8,16,32,32] f32, sigma [8,16,1024,1024] f32.
    // Identify by size to be robust to ordering.
    const float* mu    = (const float*)d_in[0];
    const float* sigma = (const float*)d_in[1];
    if (n_in >= 2 && in_sizes[0] > in_sizes[1]) {
        sigma = (const float*)d_in[0];
        mu    = (const float*)d_in[1];
    }

    float* out_mu  = (float*)d_out;            // 8*16*16*16 = 32768 elements
    float* out_sig = out_mu + 32768;           // 8*16*256*256 = 8388608 elements

    pool_argmax_kernel<<<128, 256>>>(mu, out_mu);
    sigma_gather_kernel<<<1024, 256>>>(sigma, out_sig);
}

// round 6
// speedup vs baseline: 1.1391x; 1.1304x over previous
#include <cuda_runtime.h>

// Fused: per-block recompute of 2x2 maxpool argmax indices (into smem), then
// sigma gather with explicit 8-wide load staging for MLP.
//
// Grid: 128 bc-pairs * 8 row-chunks = 1024 blocks, 256 threads.
// Thread j owns output column j; chunk owns output rows [32*chunk, 32*chunk+32).
__global__ void fused_pool_gather_kernel(const float* __restrict__ mu,
                                         const float* __restrict__ sigma,
                                         float* __restrict__ out_mu,
                                         float* __restrict__ out_sig) {
    __shared__ int scol[256];

    const int bc    = blockIdx.x >> 3;    // 0..127
    const int chunk = blockIdx.x & 7;     // 0..7
    const int j     = threadIdx.x;        // 0..255

    // ---- pool/argmax for window j (mu is 4KB/bc, L2-resident) ----
    const int ho = j >> 4;
    const int wo = j & 15;
    const float* base = mu + (size_t)bc * 1024;
    const int r0 = 2 * ho;
    const int c0 = 2 * wo;

    // Window order matches reference flatten: k = dy*2 + dx, first-max tie-break.
    const float v0 = base[r0 * 32 + c0];
    const float v1 = base[r0 * 32 + c0 + 1];
    const float v2 = base[(r0 + 1) * 32 + c0];
    const float v3 = base[(r0 + 1) * 32 + c0 + 1];

    float m = v0; int k = 0;
    if (v1 > m) { m = v1; k = 1; }
    if (v2 > m) { m = v2; k = 2; }
    if (v3 > m) { m = v3; k = 3; }

    const int cj = (r0 + (k >> 1)) * 32 + (c0 + (k & 1));   // flat idx over H*W
    scol[j] = cj;
    if (chunk == 0) out_mu[bc * 256 + j] = m;               // one writer per bc
    __syncthreads();

    // ---- gather: sigma_p[bc,i,j] = sigma[bc, scol[i], cj] ----
    const float* sbase = sigma   + ((size_t)bc << 20);      // 1024*1024 floats
    float*       obase = out_sig + (size_t)bc * 65536;
    const int i0 = chunk * 32;

    for (int ii = 0; ii < 32; ii += 8) {
        int   r[8];
        float v[8];
        #pragma unroll
        for (int t = 0; t < 8; ++t) r[t] = scol[i0 + ii + t];   // broadcast LDS
        #pragma unroll
        for (int t = 0; t < 8; ++t)                             // 8 independent LDGs in flight
            v[t] = __ldcs(sbase + ((size_t)r[t] << 10) + cj);   // .cs: single-use, evict-first
        #pragma unroll
        for (int t = 0; t < 8; ++t)                             // coalesced STG.32
            obase[(size_t)(i0 + ii + t) * 256 + j] = v[t];
    }
}

extern "C" void kernel_launch(void* const* d_in, const int* in_sizes, int n_in,
                              void* d_out, int out_size) {
    // Inputs: mu [8,16,32,32] f32, sigma [8,16,1024,1024] f32 (identify by size).
    const float* mu    = (const float*)d_in[0];
    const float* sigma = (const float*)d_in[1];
    if (n_in >= 2 && in_sizes[0] > in_sizes[1]) {
        sigma = (const float*)d_in[0];
        mu    = (const float*)d_in[1];
    }

    float* out_mu  = (float*)d_out;            // 32768 elements
    float* out_sig = out_mu + 32768;           // 8388608 elements

    fused_pool_gather_kernel<<<1024, 256>>>(mu, sigma, out_mu, out_sig);
}